// round 2
// baseline (speedup 1.0000x reference)
#include <cuda_runtime.h>

#define C_FEAT 64
#define NXc 432
#define NYc 496
#define S_CELLS (NXc * NYc)      // 214272 cells per batch element
#define SQ (S_CELLS / 4)         // 53568 float4-groups per batch element
#define MAXB 8

// Scratch: cell -> pillar-index map (or -1). 8 * 214272 * 4B = 6.86 MB.
__device__ int g_map[MAXB * S_CELLS];

__global__ void init_map_kernel(int n4) {
    int i = blockIdx.x * blockDim.x + threadIdx.x;
    if (i < n4) {
        ((int4*)g_map)[i] = make_int4(-1, -1, -1, -1);
    }
}

__global__ void scatter_idx_kernel(const int* __restrict__ coords, int P, int ncells) {
    int p = blockIdx.x * blockDim.x + threadIdx.x;
    if (p >= P) return;
    int4 c = ((const int4*)coords)[p];   // (b, z, y, x) int32
    // flat = b * (nz*nx*ny) + z + y*nx + x   (nz == 1)
    int flat = c.x * S_CELLS + c.y + c.z * NXc + c.w;
    if (flat >= 0 && flat < ncells) {    // defensive: never corrupt memory
        g_map[flat] = p;
    }
}

__global__ void __launch_bounds__(256) gather_kernel(
    const float* __restrict__ feat,   // [P, 64]
    float* __restrict__ out,          // [B, 64, NY, NX]
    int total4)
{
    int t = blockIdx.x * blockDim.x + threadIdx.x;
    if (t >= total4) return;

    int b = t / SQ;
    int q = t - b * SQ;               // float4-group index within batch: 4 consecutive x-cells

    // Read 4 cell->pillar entries with one int4 load
    int4 m = ((const int4*)(g_map + b * S_CELLS))[q];

    const float4* f0 = (const float4*)(feat + (size_t)m.x * C_FEAT);
    const float4* f1 = (const float4*)(feat + (size_t)m.y * C_FEAT);
    const float4* f2 = (const float4*)(feat + (size_t)m.z * C_FEAT);
    const float4* f3 = (const float4*)(feat + (size_t)m.w * C_FEAT);

    // Output base for this (b, spatial group); channel c lives at + c*SQ float4s
    float4* o = ((float4*)out) + (size_t)b * C_FEAT * SQ + q;

    const float4 z4 = make_float4(0.f, 0.f, 0.f, 0.f);

#pragma unroll
    for (int c4 = 0; c4 < C_FEAT / 4; ++c4) {
        float4 a  = (m.x >= 0) ? f0[c4] : z4;
        float4 bb = (m.y >= 0) ? f1[c4] : z4;
        float4 cc = (m.z >= 0) ? f2[c4] : z4;
        float4 dd = (m.w >= 0) ? f3[c4] : z4;

        // 4x4 register transpose: channel-major stores, coalesced along x
        o[(size_t)(4 * c4 + 0) * SQ] = make_float4(a.x, bb.x, cc.x, dd.x);
        o[(size_t)(4 * c4 + 1) * SQ] = make_float4(a.y, bb.y, cc.y, dd.y);
        o[(size_t)(4 * c4 + 2) * SQ] = make_float4(a.z, bb.z, cc.z, dd.z);
        o[(size_t)(4 * c4 + 3) * SQ] = make_float4(a.w, bb.w, cc.w, dd.w);
    }
}

extern "C" void kernel_launch(void* const* d_in, const int* in_sizes, int n_in,
                              void* d_out, int out_size) {
    const float* feat   = (const float*)d_in[0];
    const int*   coords = (const int*)d_in[1];

    int P = in_sizes[0] / C_FEAT;                 // number of pillars
    int B = out_size / (C_FEAT * S_CELLS);        // batch size from output shape
    if (B > MAXB) B = MAXB;

    int ncells = B * S_CELLS;
    int n4 = ncells / 4;
    init_map_kernel<<<(n4 + 255) / 256, 256>>>(n4);
    scatter_idx_kernel<<<(P + 255) / 256, 256>>>(coords, P, ncells);

    int total4 = B * SQ;
    gather_kernel<<<(total4 + 255) / 256, 256>>>(feat, (float*)d_out, total4);
}